// round 15
// baseline (speedup 1.0000x reference)
#include <cuda_runtime.h>
#include <cuda_bf16.h>
#include <cuda_fp16.h>
#include <math.h>
#include <stdint.h>

// ---------------------------------------------------------------------------
// BoundaryAwareViT — fp16 mma GEMMs; half qkv/xn/att; FFN-input LN fused
// into attn_apply_col epilogue (register-resident).
// B=32, IMG=512, P=16, D=256, DEPTH=8, G=32, N=1024, DQ=32, DF=1024, M=32768
// ---------------------------------------------------------------------------

#define Mtok  32768
#define Dd    256
#define DFf   1024
#define Nn    1024
#define QKVW  320        // 32 q + 32 k + 256 v

__device__ float  g_h   [Mtok * Dd];        // patch output
__device__ float  g_h2  [Mtok * Dd];        // residual stream
__device__ __half g_xnh [Mtok * Dd];        // LN output half
__device__ __half g_qkvh[Mtok * QKVW];      // qkv half
__device__ __half g_midh[Mtok * DFf];
__device__ __half g_atth[Mtok * 64];        // softmax weights half
__device__ float  g_wpT [Dd * Dd];          // patch weight [n][k], tf32-rounded
__device__ float  g_weT [Dd * Dd];          // edge weight [n][k], tf32-rounded
__device__ __half g_wqkvTh[8 * QKVW * Dd];  // [l][c][k] half
__device__ float  g_bqkv  [8 * QKVW];
__device__ __half g_w1Th[8 * DFf * Dd];     // [l][1024][256] half
__device__ __half g_w2Th[8 * Dd * DFf];     // [l][256][1024] half

__device__ __forceinline__ uint32_t f2tf(float f) {
    uint32_t u;
    asm("cvt.rna.tf32.f32 %0, %1;" : "=r"(u) : "f"(f));
    return u;
}
__device__ __forceinline__ float rndtf(float f) { return __uint_as_float(f2tf(f)); }

// ---------------------------------------------------------------------------
// cp.async / ldmatrix helpers
// ---------------------------------------------------------------------------
__device__ __forceinline__ void cp16(const void* s, const void* g) {
    uint32_t sa = (uint32_t)__cvta_generic_to_shared(s);
    asm volatile("cp.async.cg.shared.global [%0], [%1], 16;" :: "r"(sa), "l"(g));
}
__device__ __forceinline__ void cp16z(const void* s, const void* g, bool valid) {
    uint32_t sa = (uint32_t)__cvta_generic_to_shared(s);
    int sz = valid ? 16 : 0;
    asm volatile("cp.async.cg.shared.global [%0], [%1], 16, %2;" :: "r"(sa), "l"(g), "r"(sz));
}
#define CP_COMMIT() asm volatile("cp.async.commit_group;" ::: "memory")
#define CP_WAIT1()  asm volatile("cp.async.wait_group 1;" ::: "memory")
#define CP_WAIT0()  asm volatile("cp.async.wait_group 0;" ::: "memory")

__device__ __forceinline__ void ldsm4(uint32_t& r0, uint32_t& r1, uint32_t& r2, uint32_t& r3,
                                      uint32_t addr) {
    asm volatile("ldmatrix.sync.aligned.m8n8.x4.shared.b16 {%0,%1,%2,%3}, [%4];"
                 : "=r"(r0), "=r"(r1), "=r"(r2), "=r"(r3) : "r"(addr));
}
#define MMA_TF32(acc, a, b0, b1)                                               \
    asm volatile("mma.sync.aligned.m16n8k8.row.col.f32.tf32.tf32.f32 "         \
                 "{%0,%1,%2,%3}, {%4,%5,%6,%7}, {%8,%9}, {%0,%1,%2,%3};"       \
                 : "+f"(acc[0]), "+f"(acc[1]), "+f"(acc[2]), "+f"(acc[3])      \
                 : "r"(a[0]), "r"(a[1]), "r"(a[2]), "r"(a[3]), "r"(b0), "r"(b1))
#define MMA_F16(acc, a, b0, b1)                                                \
    asm volatile("mma.sync.aligned.m16n8k16.row.col.f32.f16.f16.f32 "          \
                 "{%0,%1,%2,%3}, {%4,%5,%6,%7}, {%8,%9}, {%0,%1,%2,%3};"       \
                 : "+f"(acc[0]), "+f"(acc[1]), "+f"(acc[2]), "+f"(acc[3])      \
                 : "r"(a[0]), "r"(a[1]), "r"(a[2]), "r"(a[3]), "r"(b0), "r"(b1))

__device__ __forceinline__ void ld_half8(const __half* p, float* f) {
    uint4 u = *(const uint4*)p;
    const __half2* h2 = (const __half2*)&u;
    float2 a = __half22float2(h2[0]);
    float2 b = __half22float2(h2[1]);
    float2 c = __half22float2(h2[2]);
    float2 d = __half22float2(h2[3]);
    f[0] = a.x; f[1] = a.y; f[2] = b.x; f[3] = b.y;
    f[4] = c.x; f[5] = c.y; f[6] = d.x; f[7] = d.y;
}

// ---------------------------------------------------------------------------
// prep kernels
// ---------------------------------------------------------------------------
__global__ void prep_all_k(const float* __restrict__ wp, const float* __restrict__ we,
                           const float* __restrict__ wq, const float* __restrict__ wk,
                           const float* __restrict__ wv, const float* __restrict__ bq,
                           const float* __restrict__ bk, const float* __restrict__ bv,
                           float* __restrict__ wpT, float* __restrict__ weT,
                           __half* __restrict__ wqkvT, float* __restrict__ bqkv)
{
    int bx = blockIdx.x, tid = threadIdx.x;
    if (bx < 256) {
        int i = bx * 256 + tid;
        wpT[i] = rndtf(wp[i]);
    } else if (bx < 320) {
        __shared__ float t[32][33];
        int tile = bx - 256;
        int r0 = (tile >> 3) * 32, c0 = (tile & 7) * 32;
        int tx = tid & 31, ty = tid >> 5;
        #pragma unroll
        for (int i = 0; i < 32; i += 8)
            t[ty + i][tx] = we[(r0 + ty + i) * 256 + c0 + tx];
        __syncthreads();
        #pragma unroll
        for (int i = 0; i < 32; i += 8)
            weT[(c0 + ty + i) * 256 + r0 + tx] = rndtf(t[tx][ty + i]);
    } else {
        int idx = (bx - 320) * 256 + tid;   // 8*320*256
        int k  = idx & 255;
        int c  = (idx >> 8) % QKVW;
        int l  = idx / (QKVW * 256);
        float val;
        if (c < 32)      val = wq[(l * 256 + k) * 32 + c];
        else if (c < 64) val = wk[(l * 256 + k) * 32 + (c - 32)];
        else             val = wv[(l * 256 + k) * 256 + (c - 64)];
        wqkvT[idx] = __float2half_rn(val);
        if (idx < 8 * QKVW) {
            int l2 = idx / QKVW, c2 = idx % QKVW;
            bqkv[idx] = (c2 < 32) ? bq[l2 * 32 + c2]
                      : (c2 < 64) ? bk[l2 * 32 + c2 - 32]
                                  : bv[l2 * 256 + c2 - 64];
        }
    }
}

__global__ void transpose_big_k(const float* __restrict__ w1, const float* __restrict__ w2,
                                __half* __restrict__ w1T, __half* __restrict__ w2T)
{
    __shared__ float t[32][33];
    int z = blockIdx.z;
    const float* src; __half* dst; int C;
    if (z < 8) { src = w1 + (size_t)z * 256 * 1024;       dst = w1T + (size_t)z * 256 * 1024;       C = 1024; if (blockIdx.y >= 8) return; }
    else       { src = w2 + (size_t)(z - 8) * 256 * 1024; dst = w2T + (size_t)(z - 8) * 256 * 1024; C = 256;  if (blockIdx.x >= 8) return; }
    int R = (z < 8) ? 256 : 1024;
    int c0 = blockIdx.x * 32, r0 = blockIdx.y * 32;
    int tx = threadIdx.x & 31, ty = threadIdx.x >> 5;
    #pragma unroll
    for (int i = 0; i < 32; i += 8)
        t[ty + i][tx] = src[(size_t)(r0 + ty + i) * C + c0 + tx];
    __syncthreads();
    #pragma unroll
    for (int i = 0; i < 32; i += 8)
        dst[(size_t)(c0 + ty + i) * R + r0 + tx] = __float2half_rn(t[tx][ty + i]);
}

// LayerNorm: warp/token, writes half xnh only. (qkv-input LN)
__global__ void ln_k(const float* __restrict__ h, __half* __restrict__ xnh,
                     const float* __restrict__ g, const float* __restrict__ b) {
    __shared__ float sg[256], sb[256];
    int tid = threadIdx.x;
    sg[tid] = g[tid];
    sb[tid] = b[tid];
    __syncthreads();
    int warp = tid >> 5, lane = tid & 31;
    int tok = blockIdx.x * 8 + warp;
    const float* hp = h + (size_t)tok * Dd + lane * 8;
    float4 v0 = *(const float4*)hp;
    float4 v1 = *(const float4*)(hp + 4);
    float s  = v0.x + v0.y + v0.z + v0.w + v1.x + v1.y + v1.z + v1.w;
    float sq = v0.x*v0.x + v0.y*v0.y + v0.z*v0.z + v0.w*v0.w
             + v1.x*v1.x + v1.y*v1.y + v1.z*v1.z + v1.w*v1.w;
    #pragma unroll
    for (int o = 16; o > 0; o >>= 1) {
        s  += __shfl_xor_sync(0xFFFFFFFFu, s,  o);
        sq += __shfl_xor_sync(0xFFFFFFFFu, sq, o);
    }
    float mean = s * (1.0f / 256.0f);
    float rstd = rsqrtf(sq * (1.0f / 256.0f) - mean * mean + 1e-5f);
    int c0 = lane * 8;
    float vals[8] = {v0.x, v0.y, v0.z, v0.w, v1.x, v1.y, v1.z, v1.w};
    union { __half hh[8]; uint4 u; } pk;
    #pragma unroll
    for (int e = 0; e < 8; e++)
        pk.hh[e] = __float2half_rn((vals[e] - mean) * rstd * sg[c0 + e] + sb[c0 + e]);
    *(uint4*)(xnh + (size_t)tok * Dd + c0) = pk.u;
}

// ---------------------------------------------------------------------------
// tf32 GEMM (patch/edge): 128x128x32, 3-stage cp.async, ldmatrix.
//   MODE 1: C = val + pos (SRC=1 im2col); 2: C = extra + tanh(val) (SRC=2 lap)
// ---------------------------------------------------------------------------
#define TS_STRIDE 36
#define T_STAGE (128 * TS_STRIDE)
#define N_STAGES 3

template<int MODE, int CVTA, int SRC>
__global__ void __launch_bounds__(256, 2)
gemm_tc(const float* __restrict__ A, const float* __restrict__ BT,
        const float* __restrict__ bias, float* __restrict__ C,
        const float* __restrict__ extra, int M, int N, int K)
{
    extern __shared__ float sm[];
    float* As = sm;
    float* Bs = sm + N_STAGES * T_STAGE;

    const int tid  = threadIdx.x;
    const int warp = tid >> 5, lane = tid & 31;
    const int wm = warp >> 2, wn = warp & 3;
    const int row0 = blockIdx.y * 128, col0 = blockIdx.x * 128;
    const int g = lane >> 2, tg = lane & 3;
    const int lr = lane & 7, sel = lane >> 3;

    float acc[4][4][4];
    #pragma unroll
    for (int i = 0; i < 4; i++)
        #pragma unroll
        for (int j = 0; j < 4; j++)
            #pragma unroll
            for (int e = 0; e < 4; e++) acc[i][j][e] = 0.0f;

    auto load_tile = [&](int stage, int k0) {
        float* as = As + stage * T_STAGE;
        float* bs = Bs + stage * T_STAGE;
        #pragma unroll
        for (int i = 0; i < 4; i++) {
            int idx = tid + i * 256;
            int r = idx >> 3, c = (idx & 7) * 4;
            if (SRC == 1) {
                int tok = row0 + r, kc = k0 + c;
                int gw = tok & 31, gh = (tok >> 5) & 31, b = tok >> 10;
                int pr = kc >> 4, pc = kc & 15;
                cp16(as + r * TS_STRIDE + c,
                     A + ((size_t)(b * 512) + gh * 16 + pr) * 512 + gw * 16 + pc);
            } else if (SRC == 2) {
                int tok = row0 + r;
                int gw = tok & 31, gh = (tok >> 5) & 31;
                const float* hp = A + (size_t)tok * 256 + (k0 + c);
                float4 ce = *(const float4*)hp;
                float4 a4 = make_float4(4.f*ce.x, 4.f*ce.y, 4.f*ce.z, 4.f*ce.w);
                if (gh > 0)  { float4 u = *(const float4*)(hp - 32*256); a4.x-=u.x; a4.y-=u.y; a4.z-=u.z; a4.w-=u.w; }
                if (gh < 31) { float4 u = *(const float4*)(hp + 32*256); a4.x-=u.x; a4.y-=u.y; a4.z-=u.z; a4.w-=u.w; }
                if (gw > 0)  { float4 u = *(const float4*)(hp - 256);    a4.x-=u.x; a4.y-=u.y; a4.z-=u.z; a4.w-=u.w; }
                if (gw < 31) { float4 u = *(const float4*)(hp + 256);    a4.x-=u.x; a4.y-=u.y; a4.z-=u.z; a4.w-=u.w; }
                float* ap = as + r * TS_STRIDE + c;
                ap[0] = rndtf(a4.x); ap[1] = rndtf(a4.y);
                ap[2] = rndtf(a4.z); ap[3] = rndtf(a4.w);
            } else {
                cp16(as + r * TS_STRIDE + c, A + (size_t)(row0 + r) * K + k0 + c);
            }
        }
        #pragma unroll
        for (int i = 0; i < 4; i++) {
            int idx = tid + i * 256;
            int r = idx >> 3, c = (idx & 7) * 4;
            cp16z(bs + r * TS_STRIDE + c, BT + (size_t)(col0 + r) * K + k0 + c,
                  (col0 + r) < N);
        }
    };

    uint32_t a_off[4], b_off[2];
    #pragma unroll
    for (int mi = 0; mi < 4; mi++) {
        int r = wm * 64 + mi * 16 + lr + (sel & 1) * 8;
        a_off[mi] = (uint32_t)((r * TS_STRIDE + (sel >> 1) * 4) * 4);
    }
    #pragma unroll
    for (int njp = 0; njp < 2; njp++) {
        int r = wn * 32 + njp * 16 + lr + (sel >> 1) * 8;
        b_off[njp] = (uint32_t)((r * TS_STRIDE + (sel & 1) * 4) * 4);
    }

    const uint32_t as_base = (uint32_t)__cvta_generic_to_shared(As);
    const uint32_t bs_base = (uint32_t)__cvta_generic_to_shared(Bs);

    const int ntiles = K >> 5;
    load_tile(0, 0);
    CP_COMMIT();
    load_tile(1, 32);
    CP_COMMIT();
    CP_WAIT1();
    __syncthreads();

    int cur = 0, nxt = 2;
    for (int t = 0; t < ntiles; t++) {
        if (t + 2 < ntiles) {
            load_tile(nxt, (t + 2) << 5);
            CP_COMMIT();
        }

        uint32_t as_st = as_base + cur * (T_STAGE * 4);
        uint32_t bs_st = bs_base + cur * (T_STAGE * 4);
        #pragma unroll
        for (int kk = 0; kk < 4; kk++) {
            const uint32_t kboff = (uint32_t)(kk * 8 * 4);
            uint32_t af[4][4], bf[4][2];
            #pragma unroll
            for (int mi = 0; mi < 4; mi++) {
                ldsm4(af[mi][0], af[mi][1], af[mi][2], af[mi][3],
                      as_st + a_off[mi] + kboff);
                if (CVTA) {
                    #pragma unroll
                    for (int e = 0; e < 4; e++)
                        af[mi][e] = f2tf(__uint_as_float(af[mi][e]));
                }
            }
            #pragma unroll
            for (int njp = 0; njp < 2; njp++)
                ldsm4(bf[2*njp][0], bf[2*njp][1], bf[2*njp+1][0], bf[2*njp+1][1],
                      bs_st + b_off[njp] + kboff);

            #pragma unroll
            for (int mi = 0; mi < 4; mi++)
                #pragma unroll
                for (int nj = 0; nj < 4; nj++)
                    MMA_TF32(acc[mi][nj], af[mi], bf[nj][0], bf[nj][1]);
        }

        if (t + 1 < ntiles) {
            if (t + 2 < ntiles) CP_WAIT1();
            else                CP_WAIT0();
            __syncthreads();
        }
        cur = (cur == N_STAGES - 1) ? 0 : cur + 1;
        nxt = (nxt == N_STAGES - 1) ? 0 : nxt + 1;
    }

    #pragma unroll
    for (int mi = 0; mi < 4; mi++) {
        #pragma unroll
        for (int nj = 0; nj < 4; nj++) {
            int r0 = row0 + wm * 64 + mi * 16 + g;
            int c0 = col0 + wn * 32 + nj * 8 + tg * 2;
            #pragma unroll
            for (int e = 0; e < 4; e++) {
                int r = r0 + (e >> 1) * 8;
                int c = c0 + (e & 1);
                if (c < N) {
                    float val = acc[mi][nj][e] + bias[c];
                    size_t idx = (size_t)r * N + c;
                    if (MODE == 1) C[idx] = val + extra[(size_t)(r & 1023) * N + c];
                    else           C[idx] = extra[idx] + tanhf(val);
                }
            }
        }
    }
}

// ---------------------------------------------------------------------------
// fp16 GEMM: 128x128x32 tiles, 3-stage cp.async, mma m16n8k16.
//   MODE 0: Ch = half(val);  3: Ch = half(gelu(val));  4: C += val (fp32)
// ---------------------------------------------------------------------------
#define HS_STRIDE 40
#define H_STAGE (128 * HS_STRIDE)     // halves per stage per matrix

template<int MODE>
__global__ void __launch_bounds__(256, 2)
gemm_hc(const __half* __restrict__ A, const __half* __restrict__ BT,
        const float* __restrict__ bias, float* __restrict__ C,
        __half* __restrict__ Ch, int M, int N, int K)
{
    extern __shared__ __half smh[];
    __half* As = smh;
    __half* Bs = smh + N_STAGES * H_STAGE;

    const int tid  = threadIdx.x;
    const int warp = tid >> 5, lane = tid & 31;
    const int wm = warp >> 2, wn = warp & 3;
    const int row0 = blockIdx.y * 128, col0 = blockIdx.x * 128;
    const int g = lane >> 2, tg = lane & 3;
    const int lr = lane & 7, sel = lane >> 3;

    float acc[4][4][4];
    #pragma unroll
    for (int i = 0; i < 4; i++)
        #pragma unroll
        for (int j = 0; j < 4; j++)
            #pragma unroll
            for (int e = 0; e < 4; e++) acc[i][j][e] = 0.0f;

    auto load_tile = [&](int stage, int k0) {
        __half* as = As + stage * H_STAGE;
        __half* bs = Bs + stage * H_STAGE;
        #pragma unroll
        for (int i = 0; i < 2; i++) {
            int idx = tid + i * 256;
            int r = idx >> 2, c = (idx & 3) * 8;
            cp16(as + r * HS_STRIDE + c, A + (size_t)(row0 + r) * K + k0 + c);
        }
        #pragma unroll
        for (int i = 0; i < 2; i++) {
            int idx = tid + i * 256;
            int r = idx >> 2, c = (idx & 3) * 8;
            cp16z(bs + r * HS_STRIDE + c, BT + (size_t)(col0 + r) * K + k0 + c,
                  (col0 + r) < N);
        }
    };

    uint32_t a_off[4], b_off[2];
    #pragma unroll
    for (int mi = 0; mi < 4; mi++) {
        int r = wm * 64 + mi * 16 + lr + (sel & 1) * 8;
        a_off[mi] = (uint32_t)((r * HS_STRIDE + (sel >> 1) * 8) * 2);
    }
    #pragma unroll
    for (int njp = 0; njp < 2; njp++) {
        int r = wn * 32 + njp * 16 + lr + (sel & 1) * 8;
        b_off[njp] = (uint32_t)((r * HS_STRIDE + (sel >> 1) * 8) * 2);
    }

    const uint32_t as_base = (uint32_t)__cvta_generic_to_shared(As);
    const uint32_t bs_base = (uint32_t)__cvta_generic_to_shared(Bs);

    const int ntiles = K >> 5;
    load_tile(0, 0);
    CP_COMMIT();
    load_tile(1, 32);
    CP_COMMIT();
    CP_WAIT1();
    __syncthreads();

    int cur = 0, nxt = 2;
    for (int t = 0; t < ntiles; t++) {
        if (t + 2 < ntiles) {
            load_tile(nxt, (t + 2) << 5);
            CP_COMMIT();
        }

        uint32_t as_st = as_base + cur * (H_STAGE * 2);
        uint32_t bs_st = bs_base + cur * (H_STAGE * 2);
        #pragma unroll
        for (int kk = 0; kk < 2; kk++) {
            const uint32_t kboff = (uint32_t)(kk * 16 * 2);
            uint32_t af[4][4], bf[4][2];
            #pragma unroll
            for (int mi = 0; mi < 4; mi++)
                ldsm4(af[mi][0], af[mi][1], af[mi][2], af[mi][3],
                      as_st + a_off[mi] + kboff);
            #pragma unroll
            for (int njp = 0; njp < 2; njp++)
                ldsm4(bf[2*njp][0], bf[2*njp+1][0], bf[2*njp][1], bf[2*njp+1][1],
                      bs_st + b_off[njp] + kboff);

            #pragma unroll
            for (int mi = 0; mi < 4; mi++)
                #pragma unroll
                for (int nj = 0; nj < 4; nj++)
                    MMA_F16(acc[mi][nj], af[mi], bf[nj][0], bf[nj][1]);
        }

        if (t + 1 < ntiles) {
            if (t + 2 < ntiles) CP_WAIT1();
            else                CP_WAIT0();
            __syncthreads();
        }
        cur = (cur == N_STAGES - 1) ? 0 : cur + 1;
        nxt = (nxt == N_STAGES - 1) ? 0 : nxt + 1;
    }

    #pragma unroll
    for (int mi = 0; mi < 4; mi++) {
        #pragma unroll
        for (int nj = 0; nj < 4; nj++) {
            int r0 = row0 + wm * 64 + mi * 16 + g;
            int c0 = col0 + wn * 32 + nj * 8 + tg * 2;
            #pragma unroll
            for (int e = 0; e < 4; e++) {
                int r = r0 + (e >> 1) * 8;
                int c = c0 + (e & 1);
                if (c < N) {
                    float val = acc[mi][nj][e] + bias[c];
                    size_t idx = (size_t)r * N + c;
                    if (MODE == 0) {
                        Ch[idx] = __float2half_rn(val);
                    } else if (MODE == 3) {
                        Ch[idx] = __float2half_rn(
                            val * 0.5f * (1.0f + erff(val * 0.70710678118654752f)));
                    } else {
                        C[idx] += val;
                    }
                }
            }
        }
    }
}

// ---------------------------------------------------------------------------
// Attention
// ---------------------------------------------------------------------------
__global__ void attn_score_k(const __half* __restrict__ qkv, __half* __restrict__ att)
{
    int warp = threadIdx.x >> 5;
    int lane = threadIdx.x & 31;
    int tok = blockIdx.x * 8 + warp;
    int gw = tok & 31, gh = (tok >> 5) & 31, b = tok >> 10;

    __shared__ float qs[8][32];
    qs[warp][lane] = __half2float(qkv[(size_t)tok * QKVW + lane]);
    __syncwarp();

    const __half* krow = qkv + (size_t)(b * Nn + gh * 32 + lane) * QKVW + 32;
    const __half* kcol = qkv + (size_t)(b * Nn + lane * 32 + gw) * QKVW + 32;
    float sr = 0.f, sc = 0.f;
    #pragma unroll
    for (int c = 0; c < 32; c += 8) {
        float kr[8], kc8[8];
        ld_half8(krow + c, kr);
        ld_half8(kcol + c, kc8);
        #pragma unroll
        for (int i = 0; i < 8; i++) {
            float q = qs[warp][c + i];
            sr = fmaf(q, kr[i], sr);
            sc = fmaf(q, kc8[i], sc);
        }
    }
    const float scale = 0.17677669529663687f;   // 1/sqrt(32)
    sr *= scale;
    sc *= scale;
    if (lane == gh) sc -= 1e9f;

    float m2 = fmaxf(sr, sc);
    #pragma unroll
    for (int o = 16; o > 0; o >>= 1) m2 = fmaxf(m2, __shfl_xor_sync(0xFFFFFFFFu, m2, o));
    float e0 = expf(sr - m2), e1 = expf(sc - m2);
    float s = e0 + e1;
    #pragma unroll
    for (int o = 16; o > 0; o >>= 1) s += __shfl_xor_sync(0xFFFFFFFFu, s, o);
    float inv = 1.0f / s;
    att[(size_t)tok * 64 + lane]      = __float2half_rn(e0 * inv);
    att[(size_t)tok * 64 + 32 + lane] = __float2half_rn(e1 * inv);
}

__global__ void attn_apply_row_k(const __half* __restrict__ att, const __half* __restrict__ qkv,
                                 const __half* __restrict__ xnh, float* __restrict__ h,
                                 const float* __restrict__ gamma_all, int layer)
{
    int blk = blockIdx.x;
    int b = blk >> 5, gh = blk & 31;
    int d = threadIdx.x;
    int base_tok = b * Nn + gh * 32;

    __shared__ float as_[32][32];
    for (int i = d; i < 1024; i += 256) {
        int t = i >> 5, j = i & 31;
        as_[t][j] = __half2float(att[(size_t)(base_tok + t) * 64 + j]);
    }
    __syncthreads();

    float acc[32];
    #pragma unroll
    for (int t = 0; t < 32; t++) acc[t] = 0.f;

    const __half* vp = qkv + (size_t)base_tok * QKVW + 64 + d;
    #pragma unroll 4
    for (int j = 0; j < 32; j++) {
        float vj = __half2float(vp[j * QKVW]);
        #pragma unroll
        for (int t = 0; t < 32; t++) acc[t] = fmaf(as_[t][j], vj, acc[t]);
    }
    float gm = gamma_all[layer];
    #pragma unroll
    for (int t = 0; t < 32; t++) {
        size_t idx = (size_t)(base_tok + t) * Dd + d;
        h[idx] += __half2float(xnh[idx]) + gm * acc[t];
    }
}

// ---------------------------------------------------------------------------
// Apply column attention + register-resident FFN-input LN.
// block = (b, gw): h += gamma*out_col; then xnh = half(LN(h)) for these tokens.
// nh stays in registers; per-token stats via shuffle + 2KB smem reduction.
// ---------------------------------------------------------------------------
__global__ void attn_apply_col_ln_k(const __half* __restrict__ att, const __half* __restrict__ qkv,
                                    float* __restrict__ h, __half* __restrict__ xnh,
                                    const float* __restrict__ gamma_all, int layer,
                                    const float* __restrict__ lg, const float* __restrict__ lb)
{
    __shared__ float as_[32][32];
    __shared__ float sg[256], sb[256];
    __shared__ float red_s[32][8], red_q[32][8];
    __shared__ float mean_s[32], rstd_s[32];

    int blk = blockIdx.x;
    int b = blk >> 5, gw = blk & 31;
    int d = threadIdx.x;
    int warp = d >> 5, lane = d & 31;

    sg[d] = lg[d];
    sb[d] = lb[d];
    for (int i = d; i < 1024; i += 256) {
        int t = i >> 5, j = i & 31;
        as_[t][j] = __half2float(att[(size_t)(b * Nn + t * 32 + gw) * 64 + 32 + j]);
    }
    __syncthreads();

    float acc[32];
    #pragma unroll
    for (int t = 0; t < 32; t++) acc[t] = 0.f;

    #pragma unroll 4
    for (int j = 0; j < 32; j++) {
        float vj = __half2float(qkv[(size_t)(b * Nn + j * 32 + gw) * QKVW + 64 + d]);
        #pragma unroll
        for (int t = 0; t < 32; t++) acc[t] = fmaf(as_[t][j], vj, acc[t]);
    }
    float gm = gamma_all[layer];
    #pragma unroll
    for (int t = 0; t < 32; t++) {
        size_t idx = (size_t)(b * Nn + t * 32 + gw) * Dd + d;
        float nh = h[idx] + gm * acc[t];
        h[idx] = nh;
        acc[t] = nh;                 // keep for LN
        float s = nh, sq = nh * nh;
        #pragma unroll
        for (int o = 16; o > 0; o >>= 1) {
            s  += __shfl_xor_sync(0xFFFFFFFFu, s,  o);
            sq += __shfl_xor_sync(0xFFFFFFFFu, sq, o);
        }
        if (lane == 0) { red_s[t][warp] = s; red_q[t][warp] = sq; }
    }
    __syncthreads();
    if (d < 32) {
        float S = 0.f, SQ = 0.f;
        #pragma unroll
        for (int w = 0; w < 8; w++) { S += red_s[d][w]; SQ += red_q[d][w]; }
        float mean = S * (1.0f / 256.0f);
        mean_s[d] = mean;
        rstd_s[d] = rsqrtf(SQ * (1.0f / 256.0f) - mean * mean + 1e-5f);
    }
    __syncthreads();
    float gd = sg[d], bd = sb[d];
    #pragma unroll
    for (int t = 0; t < 32; t++) {
        float o = (acc[t] - mean_s[t]) * rstd_s[t] * gd + bd;
        xnh[(size_t)(b * Nn + t * 32 + gw) * Dd + d] = __float2half_rn(o);
    }
}

__global__ void head_k(const float* __restrict__ h, const float* __restrict__ w,
                       const float* __restrict__ bh, float* __restrict__ out)
{
    int m = blockIdx.x;
    int d = threadIdx.x;
    float p = h[(size_t)m * Dd + d] * w[d];
    #pragma unroll
    for (int o = 16; o > 0; o >>= 1) p += __shfl_xor_sync(0xFFFFFFFFu, p, o);
    __shared__ float s1[8];
    int lane = d & 31, wr = d >> 5;
    if (lane == 0) s1[wr] = p;
    __syncthreads();
    if (d == 0) {
        float S = 0;
        #pragma unroll
        for (int i = 0; i < 8; i++) S += s1[i];
        out[m] = S + bh[0];
    }
}

// ---------------------------------------------------------------------------
extern "C" void kernel_launch(void* const* d_in, const int* in_sizes, int n_in,
                              void* d_out, int out_size)
{
    const float* x       = (const float*)d_in[0];
    const float* w_patch = (const float*)d_in[1];
    const float* b_patch = (const float*)d_in[2];
    const float* pos     = (const float*)d_in[3];
    const float* w_edge  = (const float*)d_in[4];
    const float* b_edge  = (const float*)d_in[5];
    const float* ln_g    = (const float*)d_in[6];
    const float* ln_b    = (const float*)d_in[7];
    const float* wq      = (const float*)d_in[8];
    const float* bq      = (const float*)d_in[9];
    const float* wk      = (const float*)d_in[10];
    const float* bk      = (const float*)d_in[11];
    const float* wv      = (const float*)d_in[12];
    const float* bv      = (const float*)d_in[13];
    const float* gamma   = (const float*)d_in[14];
    const float* w1      = (const float*)d_in[15];
    const float* b1      = (const float*)d_in[16];
    const float* w2      = (const float*)d_in[17];
    const float* b2      = (const float*)d_in[18];
    const float* w_head  = (const float*)d_in[19];
    const float* b_head  = (const float*)d_in[20];
    float* out = (float*)d_out;

    float *hA, *h, *wpT, *weT, *bqkv;
    __half *xnh, *qkvh, *midh, *atth, *wqkvTh, *w1Th, *w2Th;
    cudaGetSymbolAddress((void**)&hA,     g_h);
    cudaGetSymbolAddress((void**)&h,      g_h2);
    cudaGetSymbolAddress((void**)&xnh,    g_xnh);
    cudaGetSymbolAddress((void**)&qkvh,   g_qkvh);
    cudaGetSymbolAddress((void**)&midh,   g_midh);
    cudaGetSymbolAddress((void**)&atth,   g_atth);
    cudaGetSymbolAddress((void**)&wpT,    g_wpT);
    cudaGetSymbolAddress((void**)&weT,    g_weT);
    cudaGetSymbolAddress((void**)&wqkvTh, g_wqkvTh);
    cudaGetSymbolAddress((void**)&bqkv,   g_bqkv);
    cudaGetSymbolAddress((void**)&w1Th,   g_w1Th);
    cudaGetSymbolAddress((void**)&w2Th,   g_w2Th);

    const int SMEM_T = 2 * N_STAGES * T_STAGE * 4;   // 110592 B (tf32)
    const int SMEM_H = 2 * N_STAGES * H_STAGE * 2;   // 61440 B  (fp16)
    static bool attr_done = false;
    if (!attr_done) {
        cudaFuncSetAttribute(gemm_tc<1,1,1>, cudaFuncAttributeMaxDynamicSharedMemorySize, SMEM_T);
        cudaFuncSetAttribute(gemm_tc<2,0,2>, cudaFuncAttributeMaxDynamicSharedMemorySize, SMEM_T);
        cudaFuncSetAttribute(gemm_hc<0>, cudaFuncAttributeMaxDynamicSharedMemorySize, SMEM_H);
        cudaFuncSetAttribute(gemm_hc<3>, cudaFuncAttributeMaxDynamicSharedMemorySize, SMEM_H);
        cudaFuncSetAttribute(gemm_hc<4>, cudaFuncAttributeMaxDynamicSharedMemorySize, SMEM_H);
        attr_done = true;
    }

    const int M = Mtok;
    dim3 b256(256);

    // weight prep
    prep_all_k<<<2880, b256>>>(w_patch, w_edge, wq, wk, wv, bq, bk, bv,
                               wpT, weT, wqkvTh, bqkv);
    transpose_big_k<<<dim3(32, 32, 16), b256>>>(w1, w2, w1Th, w2Th);

    // patch embed (im2col fused into A load) -> hA
    gemm_tc<1,1,1><<<dim3(2, M / 128), b256, SMEM_T>>>(x, wpT, b_patch, hA, pos, M, Dd, Dd);
    // edge (laplacian fused into A load): h = hA + tanh(lap(hA) @ we + be)
    gemm_tc<2,0,2><<<dim3(2, M / 128), b256, SMEM_T>>>(hA, weT, b_edge, h, hA, M, Dd, Dd);

    for (int l = 0; l < 8; l++) {
        // qkv-input LN -> xnh
        ln_k<<<Mtok / 8, b256>>>(h, xnh, ln_g + l * Dd, ln_b + l * Dd);
        gemm_hc<0><<<dim3(3, M / 128), b256, SMEM_H>>>(
            xnh, wqkvTh + (size_t)l * QKVW * Dd, bqkv + l * QKVW, nullptr, qkvh, M, QKVW, Dd);

        attn_score_k<<<Mtok / 8, b256>>>(qkvh, atth);
        attn_apply_row_k<<<Mtok / 32, b256>>>(atth, qkvh, xnh, h, gamma, l);
        // col apply + fused FFN-input LN -> xnh (register-resident)
        attn_apply_col_ln_k<<<Mtok / 32, b256>>>(atth, qkvh, h, xnh, gamma, l,
                                                 ln_g + l * Dd, ln_b + l * Dd);

        gemm_hc<3><<<dim3(8, M / 128), b256, SMEM_H>>>(
            xnh, w1Th + (size_t)l * DFf * Dd, b1 + l * DFf, nullptr, midh, M, DFf, Dd);
        gemm_hc<4><<<dim3(2, M / 128), b256, SMEM_H>>>(
            midh, w2Th + (size_t)l * Dd * DFf, b2 + l * Dd, h, nullptr, M, Dd, DFf);
    }

    head_k<<<Mtok, b256>>>(h, w_head, b_head, out);
}

// round 17
// speedup vs baseline: 1.0033x; 1.0033x over previous
#include <cuda_runtime.h>
#include <cuda_bf16.h>
#include <cuda_fp16.h>
#include <math.h>
#include <stdint.h>

// ---------------------------------------------------------------------------
// BoundaryAwareViT — fp16 mma GEMMs; half qkv/xn/att; FFN-input LN fused into
// attn_apply_col epilogue via L2-hot global re-read (warp-per-token stats).
// B=32, IMG=512, P=16, D=256, DEPTH=8, G=32, N=1024, DQ=32, DF=1024, M=32768
// ---------------------------------------------------------------------------

#define Mtok  32768
#define Dd    256
#define DFf   1024
#define Nn    1024
#define QKVW  320        // 32 q + 32 k + 256 v

__device__ float  g_h   [Mtok * Dd];        // patch output
__device__ float  g_h2  [Mtok * Dd];        // residual stream
__device__ __half g_xnh [Mtok * Dd];        // LN output half
__device__ __half g_qkvh[Mtok * QKVW];      // qkv half
__device__ __half g_midh[Mtok * DFf];
__device__ __half g_atth[Mtok * 64];        // softmax weights half
__device__ float  g_wpT [Dd * Dd];          // patch weight [n][k], tf32-rounded
__device__ float  g_weT [Dd * Dd];          // edge weight [n][k], tf32-rounded
__device__ __half g_wqkvTh[8 * QKVW * Dd];  // [l][c][k] half
__device__ float  g_bqkv  [8 * QKVW];
__device__ __half g_w1Th[8 * DFf * Dd];     // [l][1024][256] half
__device__ __half g_w2Th[8 * Dd * DFf];     // [l][256][1024] half

__device__ __forceinline__ uint32_t f2tf(float f) {
    uint32_t u;
    asm("cvt.rna.tf32.f32 %0, %1;" : "=r"(u) : "f"(f));
    return u;
}
__device__ __forceinline__ float rndtf(float f) { return __uint_as_float(f2tf(f)); }

// ---------------------------------------------------------------------------
// cp.async / ldmatrix helpers
// ---------------------------------------------------------------------------
__device__ __forceinline__ void cp16(const void* s, const void* g) {
    uint32_t sa = (uint32_t)__cvta_generic_to_shared(s);
    asm volatile("cp.async.cg.shared.global [%0], [%1], 16;" :: "r"(sa), "l"(g));
}
__device__ __forceinline__ void cp16z(const void* s, const void* g, bool valid) {
    uint32_t sa = (uint32_t)__cvta_generic_to_shared(s);
    int sz = valid ? 16 : 0;
    asm volatile("cp.async.cg.shared.global [%0], [%1], 16, %2;" :: "r"(sa), "l"(g), "r"(sz));
}
#define CP_COMMIT() asm volatile("cp.async.commit_group;" ::: "memory")
#define CP_WAIT1()  asm volatile("cp.async.wait_group 1;" ::: "memory")
#define CP_WAIT0()  asm volatile("cp.async.wait_group 0;" ::: "memory")

__device__ __forceinline__ void ldsm4(uint32_t& r0, uint32_t& r1, uint32_t& r2, uint32_t& r3,
                                      uint32_t addr) {
    asm volatile("ldmatrix.sync.aligned.m8n8.x4.shared.b16 {%0,%1,%2,%3}, [%4];"
                 : "=r"(r0), "=r"(r1), "=r"(r2), "=r"(r3) : "r"(addr));
}
#define MMA_TF32(acc, a, b0, b1)                                               \
    asm volatile("mma.sync.aligned.m16n8k8.row.col.f32.tf32.tf32.f32 "         \
                 "{%0,%1,%2,%3}, {%4,%5,%6,%7}, {%8,%9}, {%0,%1,%2,%3};"       \
                 : "+f"(acc[0]), "+f"(acc[1]), "+f"(acc[2]), "+f"(acc[3])      \
                 : "r"(a[0]), "r"(a[1]), "r"(a[2]), "r"(a[3]), "r"(b0), "r"(b1))
#define MMA_F16(acc, a, b0, b1)                                                \
    asm volatile("mma.sync.aligned.m16n8k16.row.col.f32.f16.f16.f32 "          \
                 "{%0,%1,%2,%3}, {%4,%5,%6,%7}, {%8,%9}, {%0,%1,%2,%3};"       \
                 : "+f"(acc[0]), "+f"(acc[1]), "+f"(acc[2]), "+f"(acc[3])      \
                 : "r"(a[0]), "r"(a[1]), "r"(a[2]), "r"(a[3]), "r"(b0), "r"(b1))

__device__ __forceinline__ void ld_half8(const __half* p, float* f) {
    uint4 u = *(const uint4*)p;
    const __half2* h2 = (const __half2*)&u;
    float2 a = __half22float2(h2[0]);
    float2 b = __half22float2(h2[1]);
    float2 c = __half22float2(h2[2]);
    float2 d = __half22float2(h2[3]);
    f[0] = a.x; f[1] = a.y; f[2] = b.x; f[3] = b.y;
    f[4] = c.x; f[5] = c.y; f[6] = d.x; f[7] = d.y;
}

// ---------------------------------------------------------------------------
// prep kernels
// ---------------------------------------------------------------------------
__global__ void prep_all_k(const float* __restrict__ wp, const float* __restrict__ we,
                           const float* __restrict__ wq, const float* __restrict__ wk,
                           const float* __restrict__ wv, const float* __restrict__ bq,
                           const float* __restrict__ bk, const float* __restrict__ bv,
                           float* __restrict__ wpT, float* __restrict__ weT,
                           __half* __restrict__ wqkvT, float* __restrict__ bqkv)
{
    int bx = blockIdx.x, tid = threadIdx.x;
    if (bx < 256) {
        int i = bx * 256 + tid;
        wpT[i] = rndtf(wp[i]);
    } else if (bx < 320) {
        __shared__ float t[32][33];
        int tile = bx - 256;
        int r0 = (tile >> 3) * 32, c0 = (tile & 7) * 32;
        int tx = tid & 31, ty = tid >> 5;
        #pragma unroll
        for (int i = 0; i < 32; i += 8)
            t[ty + i][tx] = we[(r0 + ty + i) * 256 + c0 + tx];
        __syncthreads();
        #pragma unroll
        for (int i = 0; i < 32; i += 8)
            weT[(c0 + ty + i) * 256 + r0 + tx] = rndtf(t[tx][ty + i]);
    } else {
        int idx = (bx - 320) * 256 + tid;   // 8*320*256
        int k  = idx & 255;
        int c  = (idx >> 8) % QKVW;
        int l  = idx / (QKVW * 256);
        float val;
        if (c < 32)      val = wq[(l * 256 + k) * 32 + c];
        else if (c < 64) val = wk[(l * 256 + k) * 32 + (c - 32)];
        else             val = wv[(l * 256 + k) * 256 + (c - 64)];
        wqkvT[idx] = __float2half_rn(val);
        if (idx < 8 * QKVW) {
            int l2 = idx / QKVW, c2 = idx % QKVW;
            bqkv[idx] = (c2 < 32) ? bq[l2 * 32 + c2]
                      : (c2 < 64) ? bk[l2 * 32 + c2 - 32]
                                  : bv[l2 * 256 + c2 - 64];
        }
    }
}

__global__ void transpose_big_k(const float* __restrict__ w1, const float* __restrict__ w2,
                                __half* __restrict__ w1T, __half* __restrict__ w2T)
{
    __shared__ float t[32][33];
    int z = blockIdx.z;
    const float* src; __half* dst; int C;
    if (z < 8) { src = w1 + (size_t)z * 256 * 1024;       dst = w1T + (size_t)z * 256 * 1024;       C = 1024; if (blockIdx.y >= 8) return; }
    else       { src = w2 + (size_t)(z - 8) * 256 * 1024; dst = w2T + (size_t)(z - 8) * 256 * 1024; C = 256;  if (blockIdx.x >= 8) return; }
    int R = (z < 8) ? 256 : 1024;
    int c0 = blockIdx.x * 32, r0 = blockIdx.y * 32;
    int tx = threadIdx.x & 31, ty = threadIdx.x >> 5;
    #pragma unroll
    for (int i = 0; i < 32; i += 8)
        t[ty + i][tx] = src[(size_t)(r0 + ty + i) * C + c0 + tx];
    __syncthreads();
    #pragma unroll
    for (int i = 0; i < 32; i += 8)
        dst[(size_t)(c0 + ty + i) * R + r0 + tx] = __float2half_rn(t[tx][ty + i]);
}

// LayerNorm: warp/token, writes half xnh only. (qkv-input LN)
__global__ void ln_k(const float* __restrict__ h, __half* __restrict__ xnh,
                     const float* __restrict__ g, const float* __restrict__ b) {
    __shared__ float sg[256], sb[256];
    int tid = threadIdx.x;
    sg[tid] = g[tid];
    sb[tid] = b[tid];
    __syncthreads();
    int warp = tid >> 5, lane = tid & 31;
    int tok = blockIdx.x * 8 + warp;
    const float* hp = h + (size_t)tok * Dd + lane * 8;
    float4 v0 = *(const float4*)hp;
    float4 v1 = *(const float4*)(hp + 4);
    float s  = v0.x + v0.y + v0.z + v0.w + v1.x + v1.y + v1.z + v1.w;
    float sq = v0.x*v0.x + v0.y*v0.y + v0.z*v0.z + v0.w*v0.w
             + v1.x*v1.x + v1.y*v1.y + v1.z*v1.z + v1.w*v1.w;
    #pragma unroll
    for (int o = 16; o > 0; o >>= 1) {
        s  += __shfl_xor_sync(0xFFFFFFFFu, s,  o);
        sq += __shfl_xor_sync(0xFFFFFFFFu, sq, o);
    }
    float mean = s * (1.0f / 256.0f);
    float rstd = rsqrtf(sq * (1.0f / 256.0f) - mean * mean + 1e-5f);
    int c0 = lane * 8;
    float vals[8] = {v0.x, v0.y, v0.z, v0.w, v1.x, v1.y, v1.z, v1.w};
    union { __half hh[8]; uint4 u; } pk;
    #pragma unroll
    for (int e = 0; e < 8; e++)
        pk.hh[e] = __float2half_rn((vals[e] - mean) * rstd * sg[c0 + e] + sb[c0 + e]);
    *(uint4*)(xnh + (size_t)tok * Dd + c0) = pk.u;
}

// ---------------------------------------------------------------------------
// tf32 GEMM (patch/edge): 128x128x32, 3-stage cp.async, ldmatrix.
//   MODE 1: C = val + pos (SRC=1 im2col); 2: C = extra + tanh(val) (SRC=2 lap)
// ---------------------------------------------------------------------------
#define TS_STRIDE 36
#define T_STAGE (128 * TS_STRIDE)
#define N_STAGES 3

template<int MODE, int CVTA, int SRC>
__global__ void __launch_bounds__(256, 2)
gemm_tc(const float* __restrict__ A, const float* __restrict__ BT,
        const float* __restrict__ bias, float* __restrict__ C,
        const float* __restrict__ extra, int M, int N, int K)
{
    extern __shared__ float sm[];
    float* As = sm;
    float* Bs = sm + N_STAGES * T_STAGE;

    const int tid  = threadIdx.x;
    const int warp = tid >> 5, lane = tid & 31;
    const int wm = warp >> 2, wn = warp & 3;
    const int row0 = blockIdx.y * 128, col0 = blockIdx.x * 128;
    const int g = lane >> 2, tg = lane & 3;
    const int lr = lane & 7, sel = lane >> 3;

    float acc[4][4][4];
    #pragma unroll
    for (int i = 0; i < 4; i++)
        #pragma unroll
        for (int j = 0; j < 4; j++)
            #pragma unroll
            for (int e = 0; e < 4; e++) acc[i][j][e] = 0.0f;

    auto load_tile = [&](int stage, int k0) {
        float* as = As + stage * T_STAGE;
        float* bs = Bs + stage * T_STAGE;
        #pragma unroll
        for (int i = 0; i < 4; i++) {
            int idx = tid + i * 256;
            int r = idx >> 3, c = (idx & 7) * 4;
            if (SRC == 1) {
                int tok = row0 + r, kc = k0 + c;
                int gw = tok & 31, gh = (tok >> 5) & 31, b = tok >> 10;
                int pr = kc >> 4, pc = kc & 15;
                cp16(as + r * TS_STRIDE + c,
                     A + ((size_t)(b * 512) + gh * 16 + pr) * 512 + gw * 16 + pc);
            } else if (SRC == 2) {
                int tok = row0 + r;
                int gw = tok & 31, gh = (tok >> 5) & 31;
                const float* hp = A + (size_t)tok * 256 + (k0 + c);
                float4 ce = *(const float4*)hp;
                float4 a4 = make_float4(4.f*ce.x, 4.f*ce.y, 4.f*ce.z, 4.f*ce.w);
                if (gh > 0)  { float4 u = *(const float4*)(hp - 32*256); a4.x-=u.x; a4.y-=u.y; a4.z-=u.z; a4.w-=u.w; }
                if (gh < 31) { float4 u = *(const float4*)(hp + 32*256); a4.x-=u.x; a4.y-=u.y; a4.z-=u.z; a4.w-=u.w; }
                if (gw > 0)  { float4 u = *(const float4*)(hp - 256);    a4.x-=u.x; a4.y-=u.y; a4.z-=u.z; a4.w-=u.w; }
                if (gw < 31) { float4 u = *(const float4*)(hp + 256);    a4.x-=u.x; a4.y-=u.y; a4.z-=u.z; a4.w-=u.w; }
                float* ap = as + r * TS_STRIDE + c;
                ap[0] = rndtf(a4.x); ap[1] = rndtf(a4.y);
                ap[2] = rndtf(a4.z); ap[3] = rndtf(a4.w);
            } else {
                cp16(as + r * TS_STRIDE + c, A + (size_t)(row0 + r) * K + k0 + c);
            }
        }
        #pragma unroll
        for (int i = 0; i < 4; i++) {
            int idx = tid + i * 256;
            int r = idx >> 3, c = (idx & 7) * 4;
            cp16z(bs + r * TS_STRIDE + c, BT + (size_t)(col0 + r) * K + k0 + c,
                  (col0 + r) < N);
        }
    };

    uint32_t a_off[4], b_off[2];
    #pragma unroll
    for (int mi = 0; mi < 4; mi++) {
        int r = wm * 64 + mi * 16 + lr + (sel & 1) * 8;
        a_off[mi] = (uint32_t)((r * TS_STRIDE + (sel >> 1) * 4) * 4);
    }
    #pragma unroll
    for (int njp = 0; njp < 2; njp++) {
        int r = wn * 32 + njp * 16 + lr + (sel >> 1) * 8;
        b_off[njp] = (uint32_t)((r * TS_STRIDE + (sel & 1) * 4) * 4);
    }

    const uint32_t as_base = (uint32_t)__cvta_generic_to_shared(As);
    const uint32_t bs_base = (uint32_t)__cvta_generic_to_shared(Bs);

    const int ntiles = K >> 5;
    load_tile(0, 0);
    CP_COMMIT();
    load_tile(1, 32);
    CP_COMMIT();
    CP_WAIT1();
    __syncthreads();

    int cur = 0, nxt = 2;
    for (int t = 0; t < ntiles; t++) {
        if (t + 2 < ntiles) {
            load_tile(nxt, (t + 2) << 5);
            CP_COMMIT();
        }

        uint32_t as_st = as_base + cur * (T_STAGE * 4);
        uint32_t bs_st = bs_base + cur * (T_STAGE * 4);
        #pragma unroll
        for (int kk = 0; kk < 4; kk++) {
            const uint32_t kboff = (uint32_t)(kk * 8 * 4);
            uint32_t af[4][4], bf[4][2];
            #pragma unroll
            for (int mi = 0; mi < 4; mi++) {
                ldsm4(af[mi][0], af[mi][1], af[mi][2], af[mi][3],
                      as_st + a_off[mi] + kboff);
                if (CVTA) {
                    #pragma unroll
                    for (int e = 0; e < 4; e++)
                        af[mi][e] = f2tf(__uint_as_float(af[mi][e]));
                }
            }
            #pragma unroll
            for (int njp = 0; njp < 2; njp++)
                ldsm4(bf[2*njp][0], bf[2*njp][1], bf[2*njp+1][0], bf[2*njp+1][1],
                      bs_st + b_off[njp] + kboff);

            #pragma unroll
            for (int mi = 0; mi < 4; mi++)
                #pragma unroll
                for (int nj = 0; nj < 4; nj++)
                    MMA_TF32(acc[mi][nj], af[mi], bf[nj][0], bf[nj][1]);
        }

        if (t + 1 < ntiles) {
            if (t + 2 < ntiles) CP_WAIT1();
            else                CP_WAIT0();
            __syncthreads();
        }
        cur = (cur == N_STAGES - 1) ? 0 : cur + 1;
        nxt = (nxt == N_STAGES - 1) ? 0 : nxt + 1;
    }

    #pragma unroll
    for (int mi = 0; mi < 4; mi++) {
        #pragma unroll
        for (int nj = 0; nj < 4; nj++) {
            int r0 = row0 + wm * 64 + mi * 16 + g;
            int c0 = col0 + wn * 32 + nj * 8 + tg * 2;
            #pragma unroll
            for (int e = 0; e < 4; e++) {
                int r = r0 + (e >> 1) * 8;
                int c = c0 + (e & 1);
                if (c < N) {
                    float val = acc[mi][nj][e] + bias[c];
                    size_t idx = (size_t)r * N + c;
                    if (MODE == 1) C[idx] = val + extra[(size_t)(r & 1023) * N + c];
                    else           C[idx] = extra[idx] + tanhf(val);
                }
            }
        }
    }
}

// ---------------------------------------------------------------------------
// fp16 GEMM: 128x128x32 tiles, 3-stage cp.async, mma m16n8k16.
//   MODE 0: Ch = half(val);  3: Ch = half(gelu(val));  4: C += val (fp32)
// ---------------------------------------------------------------------------
#define HS_STRIDE 40
#define H_STAGE (128 * HS_STRIDE)     // halves per stage per matrix

template<int MODE>
__global__ void __launch_bounds__(256, 2)
gemm_hc(const __half* __restrict__ A, const __half* __restrict__ BT,
        const float* __restrict__ bias, float* __restrict__ C,
        __half* __restrict__ Ch, int M, int N, int K)
{
    extern __shared__ __half smh[];
    __half* As = smh;
    __half* Bs = smh + N_STAGES * H_STAGE;

    const int tid  = threadIdx.x;
    const int warp = tid >> 5, lane = tid & 31;
    const int wm = warp >> 2, wn = warp & 3;
    const int row0 = blockIdx.y * 128, col0 = blockIdx.x * 128;
    const int g = lane >> 2, tg = lane & 3;
    const int lr = lane & 7, sel = lane >> 3;

    float acc[4][4][4];
    #pragma unroll
    for (int i = 0; i < 4; i++)
        #pragma unroll
        for (int j = 0; j < 4; j++)
            #pragma unroll
            for (int e = 0; e < 4; e++) acc[i][j][e] = 0.0f;

    auto load_tile = [&](int stage, int k0) {
        __half* as = As + stage * H_STAGE;
        __half* bs = Bs + stage * H_STAGE;
        #pragma unroll
        for (int i = 0; i < 2; i++) {
            int idx = tid + i * 256;
            int r = idx >> 2, c = (idx & 3) * 8;
            cp16(as + r * HS_STRIDE + c, A + (size_t)(row0 + r) * K + k0 + c);
        }
        #pragma unroll
        for (int i = 0; i < 2; i++) {
            int idx = tid + i * 256;
            int r = idx >> 2, c = (idx & 3) * 8;
            cp16z(bs + r * HS_STRIDE + c, BT + (size_t)(col0 + r) * K + k0 + c,
                  (col0 + r) < N);
        }
    };

    uint32_t a_off[4], b_off[2];
    #pragma unroll
    for (int mi = 0; mi < 4; mi++) {
        int r = wm * 64 + mi * 16 + lr + (sel & 1) * 8;
        a_off[mi] = (uint32_t)((r * HS_STRIDE + (sel >> 1) * 8) * 2);
    }
    #pragma unroll
    for (int njp = 0; njp < 2; njp++) {
        int r = wn * 32 + njp * 16 + lr + (sel & 1) * 8;
        b_off[njp] = (uint32_t)((r * HS_STRIDE + (sel >> 1) * 8) * 2);
    }

    const uint32_t as_base = (uint32_t)__cvta_generic_to_shared(As);
    const uint32_t bs_base = (uint32_t)__cvta_generic_to_shared(Bs);

    const int ntiles = K >> 5;
    load_tile(0, 0);
    CP_COMMIT();
    load_tile(1, 32);
    CP_COMMIT();
    CP_WAIT1();
    __syncthreads();

    int cur = 0, nxt = 2;
    for (int t = 0; t < ntiles; t++) {
        if (t + 2 < ntiles) {
            load_tile(nxt, (t + 2) << 5);
            CP_COMMIT();
        }

        uint32_t as_st = as_base + cur * (H_STAGE * 2);
        uint32_t bs_st = bs_base + cur * (H_STAGE * 2);
        #pragma unroll
        for (int kk = 0; kk < 2; kk++) {
            const uint32_t kboff = (uint32_t)(kk * 16 * 2);
            uint32_t af[4][4], bf[4][2];
            #pragma unroll
            for (int mi = 0; mi < 4; mi++)
                ldsm4(af[mi][0], af[mi][1], af[mi][2], af[mi][3],
                      as_st + a_off[mi] + kboff);
            #pragma unroll
            for (int njp = 0; njp < 2; njp++)
                ldsm4(bf[2*njp][0], bf[2*njp+1][0], bf[2*njp][1], bf[2*njp+1][1],
                      bs_st + b_off[njp] + kboff);

            #pragma unroll
            for (int mi = 0; mi < 4; mi++)
                #pragma unroll
                for (int nj = 0; nj < 4; nj++)
                    MMA_F16(acc[mi][nj], af[mi], bf[nj][0], bf[nj][1]);
        }

        if (t + 1 < ntiles) {
            if (t + 2 < ntiles) CP_WAIT1();
            else                CP_WAIT0();
            __syncthreads();
        }
        cur = (cur == N_STAGES - 1) ? 0 : cur + 1;
        nxt = (nxt == N_STAGES - 1) ? 0 : nxt + 1;
    }

    #pragma unroll
    for (int mi = 0; mi < 4; mi++) {
        #pragma unroll
        for (int nj = 0; nj < 4; nj++) {
            int r0 = row0 + wm * 64 + mi * 16 + g;
            int c0 = col0 + wn * 32 + nj * 8 + tg * 2;
            #pragma unroll
            for (int e = 0; e < 4; e++) {
                int r = r0 + (e >> 1) * 8;
                int c = c0 + (e & 1);
                if (c < N) {
                    float val = acc[mi][nj][e] + bias[c];
                    size_t idx = (size_t)r * N + c;
                    if (MODE == 0) {
                        Ch[idx] = __float2half_rn(val);
                    } else if (MODE == 3) {
                        Ch[idx] = __float2half_rn(
                            val * 0.5f * (1.0f + erff(val * 0.70710678118654752f)));
                    } else {
                        C[idx] += val;
                    }
                }
            }
        }
    }
}

// ---------------------------------------------------------------------------
// Attention
// ---------------------------------------------------------------------------
__global__ void attn_score_k(const __half* __restrict__ qkv, __half* __restrict__ att)
{
    int warp = threadIdx.x >> 5;
    int lane = threadIdx.x & 31;
    int tok = blockIdx.x * 8 + warp;
    int gw = tok & 31, gh = (tok >> 5) & 31, b = tok >> 10;

    __shared__ float qs[8][32];
    qs[warp][lane] = __half2float(qkv[(size_t)tok * QKVW + lane]);
    __syncwarp();

    const __half* krow = qkv + (size_t)(b * Nn + gh * 32 + lane) * QKVW + 32;
    const __half* kcol = qkv + (size_t)(b * Nn + lane * 32 + gw) * QKVW + 32;
    float sr = 0.f, sc = 0.f;
    #pragma unroll
    for (int c = 0; c < 32; c += 8) {
        float kr[8], kc8[8];
        ld_half8(krow + c, kr);
        ld_half8(kcol + c, kc8);
        #pragma unroll
        for (int i = 0; i < 8; i++) {
            float q = qs[warp][c + i];
            sr = fmaf(q, kr[i], sr);
            sc = fmaf(q, kc8[i], sc);
        }
    }
    const float scale = 0.17677669529663687f;   // 1/sqrt(32)
    sr *= scale;
    sc *= scale;
    if (lane == gh) sc -= 1e9f;

    float m2 = fmaxf(sr, sc);
    #pragma unroll
    for (int o = 16; o > 0; o >>= 1) m2 = fmaxf(m2, __shfl_xor_sync(0xFFFFFFFFu, m2, o));
    float e0 = expf(sr - m2), e1 = expf(sc - m2);
    float s = e0 + e1;
    #pragma unroll
    for (int o = 16; o > 0; o >>= 1) s += __shfl_xor_sync(0xFFFFFFFFu, s, o);
    float inv = 1.0f / s;
    att[(size_t)tok * 64 + lane]      = __float2half_rn(e0 * inv);
    att[(size_t)tok * 64 + 32 + lane] = __float2half_rn(e1 * inv);
}

__global__ void attn_apply_row_k(const __half* __restrict__ att, const __half* __restrict__ qkv,
                                 const __half* __restrict__ xnh, float* __restrict__ h,
                                 const float* __restrict__ gamma_all, int layer)
{
    int blk = blockIdx.x;
    int b = blk >> 5, gh = blk & 31;
    int d = threadIdx.x;
    int base_tok = b * Nn + gh * 32;

    __shared__ float as_[32][32];
    for (int i = d; i < 1024; i += 256) {
        int t = i >> 5, j = i & 31;
        as_[t][j] = __half2float(att[(size_t)(base_tok + t) * 64 + j]);
    }
    __syncthreads();

    float acc[32];
    #pragma unroll
    for (int t = 0; t < 32; t++) acc[t] = 0.f;

    const __half* vp = qkv + (size_t)base_tok * QKVW + 64 + d;
    #pragma unroll 4
    for (int j = 0; j < 32; j++) {
        float vj = __half2float(vp[j * QKVW]);
        #pragma unroll
        for (int t = 0; t < 32; t++) acc[t] = fmaf(as_[t][j], vj, acc[t]);
    }
    float gm = gamma_all[layer];
    #pragma unroll
    for (int t = 0; t < 32; t++) {
        size_t idx = (size_t)(base_tok + t) * Dd + d;
        h[idx] += __half2float(xnh[idx]) + gm * acc[t];
    }
}

// ---------------------------------------------------------------------------
// Apply column attention + fused FFN-input LN via L2-hot global re-read.
// block = (b, gw): h += gamma*out_col for 32 tokens (this block writes ALL 256
// dims of those tokens); __syncthreads orders the global writes block-wide;
// then warp-per-token LN re-reads the rows (L1/L2-hot) -> xnh.
// ---------------------------------------------------------------------------
__global__ void attn_apply_col_ln_k(const __half* __restrict__ att, const __half* __restrict__ qkv,
                                    float* __restrict__ h, __half* __restrict__ xnh,
                                    const float* __restrict__ gamma_all, int layer,
                                    const float* __restrict__ lg, const float* __restrict__ lb)
{
    __shared__ float as_[32][32];
    __shared__ float sg[256], sb[256];

    int blk = blockIdx.x;
    int b = blk >> 5, gw = blk & 31;
    int d = threadIdx.x;

    sg[d] = lg[d];
    sb[d] = lb[d];
    for (int i = d; i < 1024; i += 256) {
        int t = i >> 5, j = i & 31;
        as_[t][j] = __half2float(att[(size_t)(b * Nn + t * 32 + gw) * 64 + 32 + j]);
    }
    __syncthreads();

    float acc[32];
    #pragma unroll
    for (int t = 0; t < 32; t++) acc[t] = 0.f;

    #pragma unroll 4
    for (int j = 0; j < 32; j++) {
        float vj = __half2float(qkv[(size_t)(b * Nn + j * 32 + gw) * QKVW + 64 + d]);
        #pragma unroll
        for (int t = 0; t < 32; t++) acc[t] = fmaf(as_[t][j], vj, acc[t]);
    }
    float gm = gamma_all[layer];
    #pragma unroll
    for (int t = 0; t < 32; t++) {
        size_t idx = (size_t)(b * Nn + t * 32 + gw) * Dd + d;
        h[idx] += gm * acc[t];
    }
    __syncthreads();    // h rows for this block's 32 tokens now visible block-wide

    // LN: warp per token (ln_k body), rows are L1/L2-hot
    int warp = d >> 5, lane = d & 31;
    #pragma unroll
    for (int tt = warp; tt < 32; tt += 8) {
        size_t tok = (size_t)(b * Nn + tt * 32 + gw);
        const float* hp = h + tok * Dd + lane * 8;
        float4 v0 = *(const float4*)hp;
        float4 v1 = *(const float4*)(hp + 4);
        float s  = v0.x + v0.y + v0.z + v0.w + v1.x + v1.y + v1.z + v1.w;
        float sq = v0.x*v0.x + v0.y*v0.y + v0.z*v0.z + v0.w*v0.w
                 + v1.x*v1.x + v1.y*v1.y + v1.z*v1.z + v1.w*v1.w;
        #pragma unroll
        for (int o = 16; o > 0; o >>= 1) {
            s  += __shfl_xor_sync(0xFFFFFFFFu, s,  o);
            sq += __shfl_xor_sync(0xFFFFFFFFu, sq, o);
        }
        float mean = s * (1.0f / 256.0f);
        float rstd = rsqrtf(sq * (1.0f / 256.0f) - mean * mean + 1e-5f);
        int c0 = lane * 8;
        float vals[8] = {v0.x, v0.y, v0.z, v0.w, v1.x, v1.y, v1.z, v1.w};
        union { __half hh[8]; uint4 u; } pk;
        #pragma unroll
        for (int e = 0; e < 8; e++)
            pk.hh[e] = __float2half_rn((vals[e] - mean) * rstd * sg[c0 + e] + sb[c0 + e]);
        *(uint4*)(xnh + tok * Dd + c0) = pk.u;
    }
}

__global__ void head_k(const float* __restrict__ h, const float* __restrict__ w,
                       const float* __restrict__ bh, float* __restrict__ out)
{
    int m = blockIdx.x;
    int d = threadIdx.x;
    float p = h[(size_t)m * Dd + d] * w[d];
    #pragma unroll
    for (int o = 16; o > 0; o >>= 1) p += __shfl_xor_sync(0xFFFFFFFFu, p, o);
    __shared__ float s1[8];
    int lane = d & 31, wr = d >> 5;
    if (lane == 0) s1[wr] = p;
    __syncthreads();
    if (d == 0) {
        float S = 0;
        #pragma unroll
        for (int i = 0; i < 8; i++) S += s1[i];
        out[m] = S + bh[0];
    }
}

// ---------------------------------------------------------------------------
extern "C" void kernel_launch(void* const* d_in, const int* in_sizes, int n_in,
                              void* d_out, int out_size)
{
    const float* x       = (const float*)d_in[0];
    const float* w_patch = (const float*)d_in[1];
    const float* b_patch = (const float*)d_in[2];
    const float* pos     = (const float*)d_in[3];
    const float* w_edge  = (const float*)d_in[4];
    const float* b_edge  = (const float*)d_in[5];
    const float* ln_g    = (const float*)d_in[6];
    const float* ln_b    = (const float*)d_in[7];
    const float* wq      = (const float*)d_in[8];
    const float* bq      = (const float*)d_in[9];
    const float* wk      = (const float*)d_in[10];
    const float* bk      = (const float*)d_in[11];
    const float* wv      = (const float*)d_in[12];
    const float* bv      = (const float*)d_in[13];
    const float* gamma   = (const float*)d_in[14];
    const float* w1      = (const float*)d_in[15];
    const float* b1      = (const float*)d_in[16];
    const float* w2      = (const float*)d_in[17];
    const float* b2      = (const float*)d_in[18];
    const float* w_head  = (const float*)d_in[19];
    const float* b_head  = (const float*)d_in[20];
    float* out = (float*)d_out;

    float *hA, *h, *wpT, *weT, *bqkv;
    __half *xnh, *qkvh, *midh, *atth, *wqkvTh, *w1Th, *w2Th;
    cudaGetSymbolAddress((void**)&hA,     g_h);
    cudaGetSymbolAddress((void**)&h,      g_h2);
    cudaGetSymbolAddress((void**)&xnh,    g_xnh);
    cudaGetSymbolAddress((void**)&qkvh,   g_qkvh);
    cudaGetSymbolAddress((void**)&midh,   g_midh);
    cudaGetSymbolAddress((void**)&atth,   g_atth);
    cudaGetSymbolAddress((void**)&wpT,    g_wpT);
    cudaGetSymbolAddress((void**)&weT,    g_weT);
    cudaGetSymbolAddress((void**)&wqkvTh, g_wqkvTh);
    cudaGetSymbolAddress((void**)&bqkv,   g_bqkv);
    cudaGetSymbolAddress((void**)&w1Th,   g_w1Th);
    cudaGetSymbolAddress((void**)&w2Th,   g_w2Th);

    const int SMEM_T = 2 * N_STAGES * T_STAGE * 4;   // 110592 B (tf32)
    const int SMEM_H = 2 * N_STAGES * H_STAGE * 2;   // 61440 B  (fp16)
    static bool attr_done = false;
    if (!attr_done) {
        cudaFuncSetAttribute(gemm_tc<1,1,1>, cudaFuncAttributeMaxDynamicSharedMemorySize, SMEM_T);
        cudaFuncSetAttribute(gemm_tc<2,0,2>, cudaFuncAttributeMaxDynamicSharedMemorySize, SMEM_T);
        cudaFuncSetAttribute(gemm_hc<0>, cudaFuncAttributeMaxDynamicSharedMemorySize, SMEM_H);
        cudaFuncSetAttribute(gemm_hc<3>, cudaFuncAttributeMaxDynamicSharedMemorySize, SMEM_H);
        cudaFuncSetAttribute(gemm_hc<4>, cudaFuncAttributeMaxDynamicSharedMemorySize, SMEM_H);
        attr_done = true;
    }

    const int M = Mtok;
    dim3 b256(256);

    // weight prep
    prep_all_k<<<2880, b256>>>(w_patch, w_edge, wq, wk, wv, bq, bk, bv,
                               wpT, weT, wqkvTh, bqkv);
    transpose_big_k<<<dim3(32, 32, 16), b256>>>(w1, w2, w1Th, w2Th);

    // patch embed (im2col fused into A load) -> hA
    gemm_tc<1,1,1><<<dim3(2, M / 128), b256, SMEM_T>>>(x, wpT, b_patch, hA, pos, M, Dd, Dd);
    // edge (laplacian fused into A load): h = hA + tanh(lap(hA) @ we + be)
    gemm_tc<2,0,2><<<dim3(2, M / 128), b256, SMEM_T>>>(hA, weT, b_edge, h, hA, M, Dd, Dd);

    for (int l = 0; l < 8; l++) {
        // qkv-input LN -> xnh
        ln_k<<<Mtok / 8, b256>>>(h, xnh, ln_g + l * Dd, ln_b + l * Dd);
        gemm_hc<0><<<dim3(3, M / 128), b256, SMEM_H>>>(
            xnh, wqkvTh + (size_t)l * QKVW * Dd, bqkv + l * QKVW, nullptr, qkvh, M, QKVW, Dd);

        attn_score_k<<<Mtok / 8, b256>>>(qkvh, atth);
        attn_apply_row_k<<<Mtok / 32, b256>>>(atth, qkvh, xnh, h, gamma, l);
        // col apply + fused FFN-input LN (L2-hot re-read) -> xnh
        attn_apply_col_ln_k<<<Mtok / 32, b256>>>(atth, qkvh, h, xnh, gamma, l,
                                                 ln_g + l * Dd, ln_b + l * Dd);

        gemm_hc<3><<<dim3(8, M / 128), b256, SMEM_H>>>(
            xnh, w1Th + (size_t)l * DFf * Dd, b1 + l * DFf, nullptr, midh, M, DFf, Dd);
        gemm_hc<4><<<dim3(2, M / 128), b256, SMEM_H>>>(
            midh, w2Th + (size_t)l * Dd * DFf, b2 + l * Dd, h, nullptr, M, Dd, DFf);
    }

    head_k<<<Mtok, b256>>>(h, w_head, b_head, out);
}